// round 14
// baseline (speedup 1.0000x reference)
#include <cuda_runtime.h>
#include <cstdint>

#define Bb 8
#define Nn 4096
#define Cc 8
#define Tt 256
#define NPB 64                 // n-values per block in k_reduce
#define NBLK (Nn / NPB)        // 64 n-blocks per batch
#define TQ (Tt / 4)            // 64 float4 quads over t
#define KG 8                   // k's per block in k_sig
#define TI 16                  // output rows per block in k_attn
#define KC 32                  // k-rows per staged S chunk in k_attn
#define NCH (Tt / KC)          // 8 chunks
#define SP 264                 // padded s_S row stride (floats)
#define VP 24                  // padded s_V row stride (floats)

// Per-block partial sums: [Bb*NBLK][2][Cc][TQ] float4 = 8 MB (L2-resident)
__device__ float4 g_part[Bb * NBLK * 2 * Cc * TQ];
__device__ float  g_xu1[Bb * Cc * Tt];    // x_u1 as [b][c][t]
__device__ float  g_M  [Bb * Cc * Tt];    // M[b][c][s]
__device__ float  g_S  [Bb * Tt * Tt];    // tf32-rounded sigmoid(product+bias)

// cp.async helpers
#define CP_ASYNC16(dst_u32, src_ptr) \
    asm volatile("cp.async.cg.shared.global [%0], [%1], 16;" :: "r"(dst_u32), "l"(src_ptr))
#define CP_COMMIT()  asm volatile("cp.async.commit_group;")
#define CP_WAIT(n)   asm volatile("cp.async.wait_group %0;" :: "n"(n))

__device__ __forceinline__ uint32_t f2tf32(float f) {
    uint32_t r;
    asm("cvt.rna.tf32.f32 %0, %1;" : "=r"(r) : "f"(f));
    return r;
}

__device__ __forceinline__ void mma_tf32(
    float& d0, float& d1, float& d2, float& d3,
    uint32_t a0, uint32_t a1, uint32_t a2, uint32_t a3,
    uint32_t b0, uint32_t b1)
{
    asm volatile(
        "mma.sync.aligned.m16n8k8.row.col.f32.tf32.tf32.f32 "
        "{%0,%1,%2,%3}, {%4,%5,%6,%7}, {%8,%9}, {%0,%1,%2,%3};"
        : "+f"(d0), "+f"(d1), "+f"(d2), "+f"(d3)
        : "r"(a0), "r"(a1), "r"(a2), "r"(a3), "r"(b0), "r"(b1));
}

// ---------------------------------------------------------------------------
// Kernel 1: single streaming pass over x (256 MB). (round-12 proven config)
// ---------------------------------------------------------------------------
__global__ __launch_bounds__(256, 4) void k_reduce(
    const float* __restrict__ x,  const float* __restrict__ u1,
    const float* __restrict__ u2, const float* __restrict__ u3)
{
    __shared__ float s_u1[NPB];
    __shared__ float s_u2[Cc * NPB];

    const int tid  = threadIdx.x;
    const int lane = tid & 31;
    const int warp = tid >> 5;
    const int qg   = lane & 7;
    const int cq   = lane >> 3;
    const int q    = warp * 8 + qg;

    const int b  = blockIdx.y;
    const int n0 = blockIdx.x * NPB;

    if (tid < NPB) s_u1[tid] = u1[n0 + tid];
    {
        int c = tid >> 6, nn = tid & 63;
        s_u2[c * NPB + nn]       = u2[c * Nn + n0 + nn];
        s_u2[(c + 4) * NPB + nn] = u2[(c + 4) * Nn + n0 + nn];
    }
    const float c30 = u3[2 * cq];
    const float c31 = u3[2 * cq + 1];
    __syncthreads();

    const float4* xb = (const float4*)x
                     + ((size_t)b * Nn + n0) * (Cc * TQ)
                     + (2 * cq) * TQ + q;

    float4 ax0 = make_float4(0.f, 0.f, 0.f, 0.f), ax1 = ax0;
    float4 am0 = ax0, am1 = ax0;

#pragma unroll 4
    for (int np = 0; np < NPB / 2; np++) {
        const int n = np * 2;
        const float4* xa = xb + (size_t)n * (Cc * TQ);
        const float4* xc = xa + (Cc * TQ);
        float4 v0 = __ldcs(xa);
        float4 v1 = __ldcs(xa + TQ);
        float4 w0 = __ldcs(xc);
        float4 w1 = __ldcs(xc + TQ);

        float4 r;
        r.x = v0.x * c30 + v1.x * c31;
        r.y = v0.y * c30 + v1.y * c31;
        r.z = v0.z * c30 + v1.z * c31;
        r.w = v0.w * c30 + v1.w * c31;
        r.x += __shfl_xor_sync(0xffffffffu, r.x, 8);
        r.y += __shfl_xor_sync(0xffffffffu, r.y, 8);
        r.z += __shfl_xor_sync(0xffffffffu, r.z, 8);
        r.w += __shfl_xor_sync(0xffffffffu, r.w, 8);
        r.x += __shfl_xor_sync(0xffffffffu, r.x, 16);
        r.y += __shfl_xor_sync(0xffffffffu, r.y, 16);
        r.z += __shfl_xor_sync(0xffffffffu, r.z, 16);
        r.w += __shfl_xor_sync(0xffffffffu, r.w, 16);

        float un = s_u1[n];
        ax0.x += v0.x * un;  ax0.y += v0.y * un;
        ax0.z += v0.z * un;  ax0.w += v0.w * un;
        ax1.x += v1.x * un;  ax1.y += v1.y * un;
        ax1.z += v1.z * un;  ax1.w += v1.w * un;

        float u2a = s_u2[(2 * cq) * NPB + n];
        float u2b = s_u2[(2 * cq + 1) * NPB + n];
        am0.x += r.x * u2a;  am0.y += r.y * u2a;
        am0.z += r.z * u2a;  am0.w += r.w * u2a;
        am1.x += r.x * u2b;  am1.y += r.y * u2b;
        am1.z += r.z * u2b;  am1.w += r.w * u2b;

        float4 r2;
        r2.x = w0.x * c30 + w1.x * c31;
        r2.y = w0.y * c30 + w1.y * c31;
        r2.z = w0.z * c30 + w1.z * c31;
        r2.w = w0.w * c30 + w1.w * c31;
        r2.x += __shfl_xor_sync(0xffffffffu, r2.x, 8);
        r2.y += __shfl_xor_sync(0xffffffffu, r2.y, 8);
        r2.z += __shfl_xor_sync(0xffffffffu, r2.z, 8);
        r2.w += __shfl_xor_sync(0xffffffffu, r2.w, 8);
        r2.x += __shfl_xor_sync(0xffffffffu, r2.x, 16);
        r2.y += __shfl_xor_sync(0xffffffffu, r2.y, 16);
        r2.z += __shfl_xor_sync(0xffffffffu, r2.z, 16);
        r2.w += __shfl_xor_sync(0xffffffffu, r2.w, 16);

        un = s_u1[n + 1];
        ax0.x += w0.x * un;  ax0.y += w0.y * un;
        ax0.z += w0.z * un;  ax0.w += w0.w * un;
        ax1.x += w1.x * un;  ax1.y += w1.y * un;
        ax1.z += w1.z * un;  ax1.w += w1.w * un;

        u2a = s_u2[(2 * cq) * NPB + n + 1];
        u2b = s_u2[(2 * cq + 1) * NPB + n + 1];
        am0.x += r2.x * u2a;  am0.y += r2.y * u2a;
        am0.z += r2.z * u2a;  am0.w += r2.w * u2a;
        am1.x += r2.x * u2b;  am1.y += r2.y * u2b;
        am1.z += r2.z * u2b;  am1.w += r2.w * u2b;
    }

    float4* gp = g_part + (size_t)(b * NBLK + blockIdx.x) * (2 * Cc * TQ);
    gp[(2 * cq) * TQ + q]               = ax0;
    gp[(2 * cq + 1) * TQ + q]           = ax1;
    gp[Cc * TQ + (2 * cq) * TQ + q]     = am0;
    gp[Cc * TQ + (2 * cq + 1) * TQ + q] = am1;
}

// ---------------------------------------------------------------------------
// Kernel 2: reduce 64 per-block partials -> g_xu1, g_M.
// ---------------------------------------------------------------------------
__global__ __launch_bounds__(512) void k_reduce2()
{
    __shared__ float4 red[4][128];

    const int t   = threadIdx.x;
    const int tx  = t & 127;
    const int ty  = t >> 7;
    const int idx = blockIdx.x * 128 + tx;
    const int b   = idx >> 10;
    const int rem = idx & 1023;

    const float4* gp = g_part + (size_t)b * NBLK * (2 * Cc * TQ) + rem
                     + (size_t)ty * (NBLK / 4) * (2 * Cc * TQ);
    float4 s = make_float4(0.f, 0.f, 0.f, 0.f);
#pragma unroll 8
    for (int k = 0; k < NBLK / 4; k++) {
        float4 v = gp[(size_t)k * (2 * Cc * TQ)];
        s.x += v.x; s.y += v.y; s.z += v.z; s.w += v.w;
    }
    red[ty][tx] = s;
    __syncthreads();

    if (ty == 0) {
        float4 a = red[0][tx], b2 = red[1][tx], c = red[2][tx], d = red[3][tx];
        s.x = (a.x + b2.x) + (c.x + d.x);
        s.y = (a.y + b2.y) + (c.y + d.y);
        s.z = (a.z + b2.z) + (c.z + d.z);
        s.w = (a.w + b2.w) + (c.w + d.w);
        if (rem < Cc * TQ) ((float4*)g_xu1)[b * (Cc * TQ) + rem] = s;
        else               ((float4*)g_M  )[b * (Cc * TQ) + rem - Cc * TQ] = s;
    }
}

// ---------------------------------------------------------------------------
// Kernel 3: S[b,k,j] = tf32( sigmoid( sum_c x_u1[b,c,k]*M[b,c,j] + bias ) )
// ---------------------------------------------------------------------------
__global__ __launch_bounds__(256) void k_sig(const float* __restrict__ bias)
{
    __shared__ __align__(16) float s_M[Cc * Tt];
    __shared__ __align__(16) float s_X[KG * Cc];

    const int j  = threadIdx.x;
    const int b  = blockIdx.y;
    const int k0 = blockIdx.x * KG;

    for (int idx = j; idx < Cc * Tt; idx += 256)
        s_M[idx] = g_M[b * Cc * Tt + idx];
    if (j < KG * Cc) {
        int kl = j >> 3, c = j & 7;
        s_X[kl * Cc + c] = g_xu1[b * Cc * Tt + c * Tt + (k0 + kl)];
    }
    __syncthreads();

    float rm[Cc];
#pragma unroll
    for (int c = 0; c < Cc; c++) rm[c] = s_M[c * Tt + j];

#pragma unroll
    for (int kl = 0; kl < KG; kl++) {
        float4 x0 = *(const float4*)&s_X[kl * Cc + 0];
        float4 x1 = *(const float4*)&s_X[kl * Cc + 4];
        float p = bias[(k0 + kl) * Tt + j];
        p += x0.x * rm[0] + x0.y * rm[1] + x0.z * rm[2] + x0.w * rm[3]
           + x1.x * rm[4] + x1.y * rm[5] + x1.z * rm[6] + x1.w * rm[7];
        float e = __expf(-p);
        float s = __frcp_rn(1.f + e);
        g_S[b * Tt * Tt + (k0 + kl) * Tt + j] = __uint_as_float(f2tf32(s));
    }
}

// ---------------------------------------------------------------------------
// Kernel 4: E = v @ S via tf32 mma.sync (m16n8k8), fused softmax.
// KC=32 (8 chunks), ONE barrier per chunk (wait -> sync -> issue-next ->
// compute). 256 threads = 8 warps; warp w owns n-cols [w*32, w*32+32).
// ---------------------------------------------------------------------------
__global__ __launch_bounds__(256, 1) void k_attn(
    const float* __restrict__ v, float* __restrict__ out)
{
    __shared__ __align__(16) float s_S[2][KC * SP];  // 2 x 33 KB, padded rows
    __shared__ __align__(16) float s_V[Tt * VP];     // 24 KB, [k][i], tf32

    float* s_E = &s_S[0][0];   // 16 KB E plane aliases buffer 0 after loop

    const int tid  = threadIdx.x;
    const int lane = tid & 31;
    const int w    = tid >> 5;          // warp 0..7 -> n-range w*32
    const int gid  = lane >> 2;         // 0..7
    const int tig  = lane & 3;          // 0..3
    const int b    = blockIdx.y;
    const int i0   = blockIdx.x * TI;

    const char* Sg = (const char*)(g_S + (size_t)b * Tt * Tt);
    unsigned int sb[2];
    sb[0] = (unsigned int)__cvta_generic_to_shared(&s_S[0][0]);
    sb[1] = (unsigned int)__cvta_generic_to_shared(&s_S[1][0]);

    // stage chunk 0: 32 k-rows x 256 floats -> padded rows of SP floats
    // 2048 x 16B segments, 8 per thread
#pragma unroll
    for (int p = 0; p < 8; p++) {
        int s = p * 256 + tid;          // segment id 0..2047
        int row = s >> 6, c16 = s & 63;
        CP_ASYNC16(sb[0] + (row * SP + c16 * 4) * 4, Sg + s * 16);
    }
    CP_COMMIT();

    // stage v (tf32-rounded): s_V[k*VP + il] = v[(i0+il)*Tt + k], k = tid
#pragma unroll
    for (int il = 0; il < TI; il++)
        s_V[tid * VP + il] = __uint_as_float(f2tf32(v[(i0 + il) * Tt + tid]));

    float acc[4][4];
#pragma unroll
    for (int f = 0; f < 4; f++)
#pragma unroll
        for (int r = 0; r < 4; r++) acc[f][r] = 0.f;

    for (int ch = 0; ch < NCH; ch++) {
        CP_WAIT(0);            // chunk ch resident
        __syncthreads();       // also: all readers of the other buffer passed

        if (ch + 1 < NCH) {    // refill the other buffer (readers are done)
            const char* src = Sg + (size_t)(ch + 1) * KC * Tt * 4;
            const unsigned int dst = sb[(ch + 1) & 1];
#pragma unroll
            for (int p = 0; p < 8; p++) {
                int s = p * 256 + tid;
                int row = s >> 6, c16 = s & 63;
                CP_ASYNC16(dst + (row * SP + c16 * 4) * 4, src + s * 16);
            }
            CP_COMMIT();
        }

        const float* Sc = &s_S[ch & 1][0];
#pragma unroll
        for (int kh = 0; kh < 4; kh++) {
            const int kk8 = kh * 8;            // k-step base within chunk
            const int kb  = ch * KC + kk8;     // global k base
            uint32_t a0 = __float_as_uint(s_V[(kb + tig) * VP + gid]);
            uint32_t a1 = __float_as_uint(s_V[(kb + tig) * VP + gid + 8]);
            uint32_t a2 = __float_as_uint(s_V[(kb + tig + 4) * VP + gid]);
            uint32_t a3 = __float_as_uint(s_V[(kb + tig + 4) * VP + gid + 8]);
#pragma unroll
            for (int f = 0; f < 4; f++) {
                const int n0 = w * 32 + f * 8;
                uint32_t b0 = __float_as_uint(Sc[(kk8 + tig) * SP + n0 + gid]);
                uint32_t b1 = __float_as_uint(Sc[(kk8 + tig + 4) * SP + n0 + gid]);
                mma_tf32(acc[f][0], acc[f][1], acc[f][2], acc[f][3],
                         a0, a1, a2, a3, b0, b1);
            }
        }
    }
    __syncthreads();  // all mma reads of s_S done before aliasing as s_E

    // write E: c0=(g,2t) c1=(g,2t+1) c2=(g+8,2t) c3=(g+8,2t+1)
#pragma unroll
    for (int f = 0; f < 4; f++) {
        const int n0 = w * 32 + f * 8;
        s_E[gid * Tt + n0 + 2 * tig]           = acc[f][0];
        s_E[gid * Tt + n0 + 2 * tig + 1]       = acc[f][1];
        s_E[(gid + 8) * Tt + n0 + 2 * tig]     = acc[f][2];
        s_E[(gid + 8) * Tt + n0 + 2 * tig + 1] = acc[f][3];
    }
    __syncthreads();

    // Softmax: 8 warps x 2 rows each
#pragma unroll
    for (int rr = 0; rr < 2; rr++) {
        const int row = w * 2 + rr;
        float m = -1e30f;
#pragma unroll
        for (int qi = 0; qi < Tt / 32; qi++)
            m = fmaxf(m, s_E[row * Tt + qi * 32 + lane]);
#pragma unroll
        for (int off = 16; off > 0; off >>= 1)
            m = fmaxf(m, __shfl_xor_sync(0xffffffffu, m, off));

        float e[Tt / 32];
        float sum = 0.f;
#pragma unroll
        for (int qi = 0; qi < Tt / 32; qi++) {
            e[qi] = __expf(s_E[row * Tt + qi * 32 + lane] - m);
            sum += e[qi];
        }
#pragma unroll
        for (int off = 16; off > 0; off >>= 1)
            sum += __shfl_xor_sync(0xffffffffu, sum, off);

        const float inv = __frcp_rn(sum);
        const size_t o = ((size_t)b * Tt + (i0 + row)) * Tt;
#pragma unroll
        for (int qi = 0; qi < Tt / 32; qi++)
            out[o + qi * 32 + lane] = e[qi] * inv;
    }
}

// ---------------------------------------------------------------------------
extern "C" void kernel_launch(void* const* d_in, const int* in_sizes, int n_in,
                              void* d_out, int out_size)
{
    const float* x  = (const float*)d_in[0];
    const float* u1 = (const float*)d_in[1];
    const float* u2 = (const float*)d_in[2];
    const float* u3 = (const float*)d_in[3];
    const float* bb = (const float*)d_in[4];
    const float* v  = (const float*)d_in[5];
    float* out = (float*)d_out;

    dim3 g1(NBLK, Bb);              // 512 blocks
    k_reduce<<<g1, 256>>>(x, u1, u2, u3);

    k_reduce2<<<64, 512>>>();

    dim3 g2(Tt / KG, Bb);           // 256 blocks
    k_sig<<<g2, 256>>>(bb);

    dim3 g3(Tt / TI, Bb);           // 128 blocks, 256 threads
    k_attn<<<g3, 256>>>(v, out);
}

// round 15
// speedup vs baseline: 1.0060x; 1.0060x over previous
#include <cuda_runtime.h>
#include <cstdint>

#define Bb 8
#define Nn 4096
#define Cc 8
#define Tt 256
#define NPB 64                 // n-values per block in k_reduce
#define NBLK (Nn / NPB)        // 64 n-blocks per batch
#define TQ (Tt / 4)            // 64 float4 quads over t
#define KG 8                   // k's per block in k_sig
#define TI 16                  // output rows per block in k_attn
#define KC 16                  // k-rows per staged S chunk in k_attn
#define NCH (Tt / KC)          // 16 chunks
#define NST 4                  // pipeline stages (smem buffers)
#define SP 264                 // padded s_S row stride (floats)
#define VP 24                  // padded s_V row stride (floats)

// Per-block partial sums: [Bb*NBLK][2][Cc][TQ] float4 = 8 MB (L2-resident)
__device__ float4 g_part[Bb * NBLK * 2 * Cc * TQ];
__device__ float  g_xu1[Bb * Cc * Tt];    // x_u1 as [b][c][t]
__device__ float  g_M  [Bb * Cc * Tt];    // M[b][c][s]
__device__ float  g_S  [Bb * Tt * Tt];    // tf32-rounded sigmoid(product+bias)

// cp.async helpers
#define CP_ASYNC16(dst_u32, src_ptr) \
    asm volatile("cp.async.cg.shared.global [%0], [%1], 16;" :: "r"(dst_u32), "l"(src_ptr))
#define CP_COMMIT()  asm volatile("cp.async.commit_group;")
#define CP_WAIT(n)   asm volatile("cp.async.wait_group %0;" :: "n"(n))

__device__ __forceinline__ uint32_t f2tf32(float f) {
    uint32_t r;
    asm("cvt.rna.tf32.f32 %0, %1;" : "=r"(r) : "f"(f));
    return r;
}

__device__ __forceinline__ void mma_tf32(
    float& d0, float& d1, float& d2, float& d3,
    uint32_t a0, uint32_t a1, uint32_t a2, uint32_t a3,
    uint32_t b0, uint32_t b1)
{
    asm volatile(
        "mma.sync.aligned.m16n8k8.row.col.f32.tf32.tf32.f32 "
        "{%0,%1,%2,%3}, {%4,%5,%6,%7}, {%8,%9}, {%0,%1,%2,%3};"
        : "+f"(d0), "+f"(d1), "+f"(d2), "+f"(d3)
        : "r"(a0), "r"(a1), "r"(a2), "r"(a3), "r"(b0), "r"(b1));
}

// ---------------------------------------------------------------------------
// Kernel 1: single streaming pass over x (256 MB). (round-12 proven config)
// ---------------------------------------------------------------------------
__global__ __launch_bounds__(256, 4) void k_reduce(
    const float* __restrict__ x,  const float* __restrict__ u1,
    const float* __restrict__ u2, const float* __restrict__ u3)
{
    __shared__ float s_u1[NPB];
    __shared__ float s_u2[Cc * NPB];

    const int tid  = threadIdx.x;
    const int lane = tid & 31;
    const int warp = tid >> 5;
    const int qg   = lane & 7;
    const int cq   = lane >> 3;
    const int q    = warp * 8 + qg;

    const int b  = blockIdx.y;
    const int n0 = blockIdx.x * NPB;

    if (tid < NPB) s_u1[tid] = u1[n0 + tid];
    {
        int c = tid >> 6, nn = tid & 63;
        s_u2[c * NPB + nn]       = u2[c * Nn + n0 + nn];
        s_u2[(c + 4) * NPB + nn] = u2[(c + 4) * Nn + n0 + nn];
    }
    const float c30 = u3[2 * cq];
    const float c31 = u3[2 * cq + 1];
    __syncthreads();

    const float4* xb = (const float4*)x
                     + ((size_t)b * Nn + n0) * (Cc * TQ)
                     + (2 * cq) * TQ + q;

    float4 ax0 = make_float4(0.f, 0.f, 0.f, 0.f), ax1 = ax0;
    float4 am0 = ax0, am1 = ax0;

#pragma unroll 4
    for (int np = 0; np < NPB / 2; np++) {
        const int n = np * 2;
        const float4* xa = xb + (size_t)n * (Cc * TQ);
        const float4* xc = xa + (Cc * TQ);
        float4 v0 = __ldcs(xa);
        float4 v1 = __ldcs(xa + TQ);
        float4 w0 = __ldcs(xc);
        float4 w1 = __ldcs(xc + TQ);

        float4 r;
        r.x = v0.x * c30 + v1.x * c31;
        r.y = v0.y * c30 + v1.y * c31;
        r.z = v0.z * c30 + v1.z * c31;
        r.w = v0.w * c30 + v1.w * c31;
        r.x += __shfl_xor_sync(0xffffffffu, r.x, 8);
        r.y += __shfl_xor_sync(0xffffffffu, r.y, 8);
        r.z += __shfl_xor_sync(0xffffffffu, r.z, 8);
        r.w += __shfl_xor_sync(0xffffffffu, r.w, 8);
        r.x += __shfl_xor_sync(0xffffffffu, r.x, 16);
        r.y += __shfl_xor_sync(0xffffffffu, r.y, 16);
        r.z += __shfl_xor_sync(0xffffffffu, r.z, 16);
        r.w += __shfl_xor_sync(0xffffffffu, r.w, 16);

        float un = s_u1[n];
        ax0.x += v0.x * un;  ax0.y += v0.y * un;
        ax0.z += v0.z * un;  ax0.w += v0.w * un;
        ax1.x += v1.x * un;  ax1.y += v1.y * un;
        ax1.z += v1.z * un;  ax1.w += v1.w * un;

        float u2a = s_u2[(2 * cq) * NPB + n];
        float u2b = s_u2[(2 * cq + 1) * NPB + n];
        am0.x += r.x * u2a;  am0.y += r.y * u2a;
        am0.z += r.z * u2a;  am0.w += r.w * u2a;
        am1.x += r.x * u2b;  am1.y += r.y * u2b;
        am1.z += r.z * u2b;  am1.w += r.w * u2b;

        float4 r2;
        r2.x = w0.x * c30 + w1.x * c31;
        r2.y = w0.y * c30 + w1.y * c31;
        r2.z = w0.z * c30 + w1.z * c31;
        r2.w = w0.w * c30 + w1.w * c31;
        r2.x += __shfl_xor_sync(0xffffffffu, r2.x, 8);
        r2.y += __shfl_xor_sync(0xffffffffu, r2.y, 8);
        r2.z += __shfl_xor_sync(0xffffffffu, r2.z, 8);
        r2.w += __shfl_xor_sync(0xffffffffu, r2.w, 8);
        r2.x += __shfl_xor_sync(0xffffffffu, r2.x, 16);
        r2.y += __shfl_xor_sync(0xffffffffu, r2.y, 16);
        r2.z += __shfl_xor_sync(0xffffffffu, r2.z, 16);
        r2.w += __shfl_xor_sync(0xffffffffu, r2.w, 16);

        un = s_u1[n + 1];
        ax0.x += w0.x * un;  ax0.y += w0.y * un;
        ax0.z += w0.z * un;  ax0.w += w0.w * un;
        ax1.x += w1.x * un;  ax1.y += w1.y * un;
        ax1.z += w1.z * un;  ax1.w += w1.w * un;

        u2a = s_u2[(2 * cq) * NPB + n + 1];
        u2b = s_u2[(2 * cq + 1) * NPB + n + 1];
        am0.x += r2.x * u2a;  am0.y += r2.y * u2a;
        am0.z += r2.z * u2a;  am0.w += r2.w * u2a;
        am1.x += r2.x * u2b;  am1.y += r2.y * u2b;
        am1.z += r2.z * u2b;  am1.w += r2.w * u2b;
    }

    float4* gp = g_part + (size_t)(b * NBLK + blockIdx.x) * (2 * Cc * TQ);
    gp[(2 * cq) * TQ + q]               = ax0;
    gp[(2 * cq + 1) * TQ + q]           = ax1;
    gp[Cc * TQ + (2 * cq) * TQ + q]     = am0;
    gp[Cc * TQ + (2 * cq + 1) * TQ + q] = am1;
}

// ---------------------------------------------------------------------------
// Kernel 2: reduce 64 per-block partials -> g_xu1, g_M.
// ---------------------------------------------------------------------------
__global__ __launch_bounds__(512) void k_reduce2()
{
    __shared__ float4 red[4][128];

    const int t   = threadIdx.x;
    const int tx  = t & 127;
    const int ty  = t >> 7;
    const int idx = blockIdx.x * 128 + tx;
    const int b   = idx >> 10;
    const int rem = idx & 1023;

    const float4* gp = g_part + (size_t)b * NBLK * (2 * Cc * TQ) + rem
                     + (size_t)ty * (NBLK / 4) * (2 * Cc * TQ);
    float4 s = make_float4(0.f, 0.f, 0.f, 0.f);
#pragma unroll 8
    for (int k = 0; k < NBLK / 4; k++) {
        float4 v = gp[(size_t)k * (2 * Cc * TQ)];
        s.x += v.x; s.y += v.y; s.z += v.z; s.w += v.w;
    }
    red[ty][tx] = s;
    __syncthreads();

    if (ty == 0) {
        float4 a = red[0][tx], b2 = red[1][tx], c = red[2][tx], d = red[3][tx];
        s.x = (a.x + b2.x) + (c.x + d.x);
        s.y = (a.y + b2.y) + (c.y + d.y);
        s.z = (a.z + b2.z) + (c.z + d.z);
        s.w = (a.w + b2.w) + (c.w + d.w);
        if (rem < Cc * TQ) ((float4*)g_xu1)[b * (Cc * TQ) + rem] = s;
        else               ((float4*)g_M  )[b * (Cc * TQ) + rem - Cc * TQ] = s;
    }
}

// ---------------------------------------------------------------------------
// Kernel 3: S[b,k,j] = tf32( sigmoid( sum_c x_u1[b,c,k]*M[b,c,j] + bias ) )
// ---------------------------------------------------------------------------
__global__ __launch_bounds__(256) void k_sig(const float* __restrict__ bias)
{
    __shared__ __align__(16) float s_M[Cc * Tt];
    __shared__ __align__(16) float s_X[KG * Cc];

    const int j  = threadIdx.x;
    const int b  = blockIdx.y;
    const int k0 = blockIdx.x * KG;

    for (int idx = j; idx < Cc * Tt; idx += 256)
        s_M[idx] = g_M[b * Cc * Tt + idx];
    if (j < KG * Cc) {
        int kl = j >> 3, c = j & 7;
        s_X[kl * Cc + c] = g_xu1[b * Cc * Tt + c * Tt + (k0 + kl)];
    }
    __syncthreads();

    float rm[Cc];
#pragma unroll
    for (int c = 0; c < Cc; c++) rm[c] = s_M[c * Tt + j];

#pragma unroll
    for (int kl = 0; kl < KG; kl++) {
        float4 x0 = *(const float4*)&s_X[kl * Cc + 0];
        float4 x1 = *(const float4*)&s_X[kl * Cc + 4];
        float p = bias[(k0 + kl) * Tt + j];
        p += x0.x * rm[0] + x0.y * rm[1] + x0.z * rm[2] + x0.w * rm[3]
           + x1.x * rm[4] + x1.y * rm[5] + x1.z * rm[6] + x1.w * rm[7];
        float e = __expf(-p);
        float s = __frcp_rn(1.f + e);
        g_S[b * Tt * Tt + (k0 + kl) * Tt + j] = __uint_as_float(f2tf32(s));
    }
}

// ---------------------------------------------------------------------------
// Kernel 4: E = v @ S via tf32 mma.sync (m16n8k8), fused softmax.
// 4-stage cp.async pipeline: chunks 0-2 issued up front, WAIT(2) keeps two
// loads in flight behind the one being computed -> loads stream back-to-back.
// ---------------------------------------------------------------------------
__global__ __launch_bounds__(256, 1) void k_attn(
    const float* __restrict__ v, float* __restrict__ out)
{
    __shared__ __align__(16) float s_S[NST][KC * SP];  // 4 x 16.9 KB
    __shared__ __align__(16) float s_V[Tt * VP];       // 24 KB, [k][i], tf32

    float* s_E = &s_S[0][0];   // 16 KB E plane aliases buffer 0 after loop

    const int tid  = threadIdx.x;
    const int lane = tid & 31;
    const int w    = tid >> 5;          // warp 0..7 -> n-range w*32
    const int gid  = lane >> 2;         // 0..7
    const int tig  = lane & 3;          // 0..3
    const int b    = blockIdx.y;
    const int i0   = blockIdx.x * TI;

    const char* Sg = (const char*)(g_S + (size_t)b * Tt * Tt);
    unsigned int sb[NST];
#pragma unroll
    for (int s = 0; s < NST; s++)
        sb[s] = (unsigned int)__cvta_generic_to_shared(&s_S[s][0]);

    // prologue: issue chunks 0..2 (each 16 rows x 256 floats = 1024 segs, 4/thread)
#pragma unroll
    for (int c = 0; c < NST - 1; c++) {
        const char* src = Sg + (size_t)c * KC * Tt * 4;
#pragma unroll
        for (int p = 0; p < 4; p++) {
            int s = p * 256 + tid;          // segment id 0..1023
            int row = s >> 6, c16 = s & 63;
            CP_ASYNC16(sb[c] + (row * SP + c16 * 4) * 4, src + s * 16);
        }
        CP_COMMIT();
    }

    // stage v (tf32-rounded): s_V[k*VP + il] = v[(i0+il)*Tt + k], k = tid
#pragma unroll
    for (int il = 0; il < TI; il++)
        s_V[tid * VP + il] = __uint_as_float(f2tf32(v[(i0 + il) * Tt + tid]));

    float acc[4][4];
#pragma unroll
    for (int f = 0; f < 4; f++)
#pragma unroll
        for (int r = 0; r < 4; r++) acc[f][r] = 0.f;

    for (int ch = 0; ch < NCH; ch++) {
        // chunk ch must be resident; allow the newest in-flight loads to pend
        if (ch <= NCH - 3)      { CP_WAIT(2); }
        else if (ch == NCH - 2) { CP_WAIT(1); }
        else                    { CP_WAIT(0); }
        __syncthreads();   // all readers of buffer (ch+3)&3 (chunk ch-1) passed

        if (ch + NST - 1 < NCH) {   // issue chunk ch+3 into its buffer
            const int cn = ch + NST - 1;
            const char* src = Sg + (size_t)cn * KC * Tt * 4;
            const unsigned int dst = sb[cn & (NST - 1)];
#pragma unroll
            for (int p = 0; p < 4; p++) {
                int s = p * 256 + tid;
                int row = s >> 6, c16 = s & 63;
                CP_ASYNC16(dst + (row * SP + c16 * 4) * 4, src + s * 16);
            }
            CP_COMMIT();
        }

        const float* Sc = &s_S[ch & (NST - 1)][0];
#pragma unroll
        for (int kh = 0; kh < 2; kh++) {
            const int kk8 = kh * 8;
            const int kb  = ch * KC + kk8;
            uint32_t a0 = __float_as_uint(s_V[(kb + tig) * VP + gid]);
            uint32_t a1 = __float_as_uint(s_V[(kb + tig) * VP + gid + 8]);
            uint32_t a2 = __float_as_uint(s_V[(kb + tig + 4) * VP + gid]);
            uint32_t a3 = __float_as_uint(s_V[(kb + tig + 4) * VP + gid + 8]);
#pragma unroll
            for (int f = 0; f < 4; f++) {
                const int n0 = w * 32 + f * 8;
                uint32_t b0 = __float_as_uint(Sc[(kk8 + tig) * SP + n0 + gid]);
                uint32_t b1 = __float_as_uint(Sc[(kk8 + tig + 4) * SP + n0 + gid]);
                mma_tf32(acc[f][0], acc[f][1], acc[f][2], acc[f][3],
                         a0, a1, a2, a3, b0, b1);
            }
        }
    }
    __syncthreads();  // all mma reads of s_S done before aliasing as s_E

    // write E: c0=(g,2t) c1=(g,2t+1) c2=(g+8,2t) c3=(g+8,2t+1)
#pragma unroll
    for (int f = 0; f < 4; f++) {
        const int n0 = w * 32 + f * 8;
        s_E[gid * Tt + n0 + 2 * tig]           = acc[f][0];
        s_E[gid * Tt + n0 + 2 * tig + 1]       = acc[f][1];
        s_E[(gid + 8) * Tt + n0 + 2 * tig]     = acc[f][2];
        s_E[(gid + 8) * Tt + n0 + 2 * tig + 1] = acc[f][3];
    }
    __syncthreads();

    // Softmax: 8 warps x 2 rows each
#pragma unroll
    for (int rr = 0; rr < 2; rr++) {
        const int row = w * 2 + rr;
        float m = -1e30f;
#pragma unroll
        for (int qi = 0; qi < Tt / 32; qi++)
            m = fmaxf(m, s_E[row * Tt + qi * 32 + lane]);
#pragma unroll
        for (int off = 16; off > 0; off >>= 1)
            m = fmaxf(m, __shfl_xor_sync(0xffffffffu, m, off));

        float e[Tt / 32];
        float sum = 0.f;
#pragma unroll
        for (int qi = 0; qi < Tt / 32; qi++) {
            e[qi] = __expf(s_E[row * Tt + qi * 32 + lane] - m);
            sum += e[qi];
        }
#pragma unroll
        for (int off = 16; off > 0; off >>= 1)
            sum += __shfl_xor_sync(0xffffffffu, sum, off);

        const float inv = __frcp_rn(sum);
        const size_t o = ((size_t)b * Tt + (i0 + row)) * Tt;
#pragma unroll
        for (int qi = 0; qi < Tt / 32; qi++)
            out[o + qi * 32 + lane] = e[qi] * inv;
    }
}

// ---------------------------------------------------------------------------
extern "C" void kernel_launch(void* const* d_in, const int* in_sizes, int n_in,
                              void* d_out, int out_size)
{
    const float* x  = (const float*)d_in[0];
    const float* u1 = (const float*)d_in[1];
    const float* u2 = (const float*)d_in[2];
    const float* u3 = (const float*)d_in[3];
    const float* bb = (const float*)d_in[4];
    const float* v  = (const float*)d_in[5];
    float* out = (float*)d_out;

    dim3 g1(NBLK, Bb);              // 512 blocks
    k_reduce<<<g1, 256>>>(x, u1, u2, u3);

    k_reduce2<<<64, 512>>>();

    dim3 g2(Tt / KG, Bb);           // 256 blocks
    k_sig<<<g2, 256>>>(bb);

    dim3 g3(Tt / TI, Bb);           // 128 blocks, 256 threads
    k_attn<<<g3, 256>>>(v, out);
}

// round 16
// speedup vs baseline: 1.0372x; 1.0310x over previous
#include <cuda_runtime.h>
#include <cstdint>

#define Bb 8
#define Nn 4096
#define Cc 8
#define Tt 256
#define NPB 64                 // n-values per block in k_reduce
#define NBLK (Nn / NPB)        // 64 n-blocks per batch
#define TQ (Tt / 4)            // 64 float4 quads over t
#define KG 8                   // k's per block in k_sig
#define TI 16                  // output rows per block in k_attn
#define KC 32                  // k-rows per staged S chunk in k_attn
#define NCH (Tt / KC)          // 8 chunks
#define NST 3                  // pipeline stages (smem buffers)
#define SP 264                 // padded s_S row stride (floats)
#define VP 24                  // padded s_V row stride (floats)

// Per-block partial sums: [Bb*NBLK][2][Cc][TQ] float4 = 8 MB (L2-resident)
__device__ float4 g_part[Bb * NBLK * 2 * Cc * TQ];
__device__ float  g_xu1[Bb * Cc * Tt];    // x_u1 as [b][c][t]
__device__ float  g_M  [Bb * Cc * Tt];    // M[b][c][s]
__device__ float  g_S  [Bb * Tt * Tt];    // tf32-rounded sigmoid(product+bias)

// cp.async helpers
#define CP_ASYNC16(dst_u32, src_ptr) \
    asm volatile("cp.async.cg.shared.global [%0], [%1], 16;" :: "r"(dst_u32), "l"(src_ptr))
#define CP_COMMIT()  asm volatile("cp.async.commit_group;")
#define CP_WAIT(n)   asm volatile("cp.async.wait_group %0;" :: "n"(n))

// PDL (programmatic dependent launch) controls
#define PDL_LAUNCH_DEPENDENTS() asm volatile("griddepcontrol.launch_dependents;")
#define PDL_WAIT()              asm volatile("griddepcontrol.wait;")

__device__ __forceinline__ uint32_t f2tf32(float f) {
    uint32_t r;
    asm("cvt.rna.tf32.f32 %0, %1;" : "=r"(r) : "f"(f));
    return r;
}

__device__ __forceinline__ void mma_tf32(
    float& d0, float& d1, float& d2, float& d3,
    uint32_t a0, uint32_t a1, uint32_t a2, uint32_t a3,
    uint32_t b0, uint32_t b1)
{
    asm volatile(
        "mma.sync.aligned.m16n8k8.row.col.f32.tf32.tf32.f32 "
        "{%0,%1,%2,%3}, {%4,%5,%6,%7}, {%8,%9}, {%0,%1,%2,%3};"
        : "+f"(d0), "+f"(d1), "+f"(d2), "+f"(d3)
        : "r"(a0), "r"(a1), "r"(a2), "r"(a3), "r"(b0), "r"(b1));
}

// ---------------------------------------------------------------------------
// Kernel 1: single streaming pass over x (256 MB). (round-12 proven config)
// ---------------------------------------------------------------------------
__global__ __launch_bounds__(256, 4) void k_reduce(
    const float* __restrict__ x,  const float* __restrict__ u1,
    const float* __restrict__ u2, const float* __restrict__ u3)
{
    __shared__ float s_u1[NPB];
    __shared__ float s_u2[Cc * NPB];

    PDL_LAUNCH_DEPENDENTS();   // let k_reduce2 launch & prologue early

    const int tid  = threadIdx.x;
    const int lane = tid & 31;
    const int warp = tid >> 5;
    const int qg   = lane & 7;
    const int cq   = lane >> 3;
    const int q    = warp * 8 + qg;

    const int b  = blockIdx.y;
    const int n0 = blockIdx.x * NPB;

    if (tid < NPB) s_u1[tid] = u1[n0 + tid];
    {
        int c = tid >> 6, nn = tid & 63;
        s_u2[c * NPB + nn]       = u2[c * Nn + n0 + nn];
        s_u2[(c + 4) * NPB + nn] = u2[(c + 4) * Nn + n0 + nn];
    }
    const float c30 = u3[2 * cq];
    const float c31 = u3[2 * cq + 1];
    __syncthreads();

    const float4* xb = (const float4*)x
                     + ((size_t)b * Nn + n0) * (Cc * TQ)
                     + (2 * cq) * TQ + q;

    float4 ax0 = make_float4(0.f, 0.f, 0.f, 0.f), ax1 = ax0;
    float4 am0 = ax0, am1 = ax0;

#pragma unroll 4
    for (int np = 0; np < NPB / 2; np++) {
        const int n = np * 2;
        const float4* xa = xb + (size_t)n * (Cc * TQ);
        const float4* xc = xa + (Cc * TQ);
        float4 v0 = __ldcs(xa);
        float4 v1 = __ldcs(xa + TQ);
        float4 w0 = __ldcs(xc);
        float4 w1 = __ldcs(xc + TQ);

        float4 r;
        r.x = v0.x * c30 + v1.x * c31;
        r.y = v0.y * c30 + v1.y * c31;
        r.z = v0.z * c30 + v1.z * c31;
        r.w = v0.w * c30 + v1.w * c31;
        r.x += __shfl_xor_sync(0xffffffffu, r.x, 8);
        r.y += __shfl_xor_sync(0xffffffffu, r.y, 8);
        r.z += __shfl_xor_sync(0xffffffffu, r.z, 8);
        r.w += __shfl_xor_sync(0xffffffffu, r.w, 8);
        r.x += __shfl_xor_sync(0xffffffffu, r.x, 16);
        r.y += __shfl_xor_sync(0xffffffffu, r.y, 16);
        r.z += __shfl_xor_sync(0xffffffffu, r.z, 16);
        r.w += __shfl_xor_sync(0xffffffffu, r.w, 16);

        float un = s_u1[n];
        ax0.x += v0.x * un;  ax0.y += v0.y * un;
        ax0.z += v0.z * un;  ax0.w += v0.w * un;
        ax1.x += v1.x * un;  ax1.y += v1.y * un;
        ax1.z += v1.z * un;  ax1.w += v1.w * un;

        float u2a = s_u2[(2 * cq) * NPB + n];
        float u2b = s_u2[(2 * cq + 1) * NPB + n];
        am0.x += r.x * u2a;  am0.y += r.y * u2a;
        am0.z += r.z * u2a;  am0.w += r.w * u2a;
        am1.x += r.x * u2b;  am1.y += r.y * u2b;
        am1.z += r.z * u2b;  am1.w += r.w * u2b;

        float4 r2;
        r2.x = w0.x * c30 + w1.x * c31;
        r2.y = w0.y * c30 + w1.y * c31;
        r2.z = w0.z * c30 + w1.z * c31;
        r2.w = w0.w * c30 + w1.w * c31;
        r2.x += __shfl_xor_sync(0xffffffffu, r2.x, 8);
        r2.y += __shfl_xor_sync(0xffffffffu, r2.y, 8);
        r2.z += __shfl_xor_sync(0xffffffffu, r2.z, 8);
        r2.w += __shfl_xor_sync(0xffffffffu, r2.w, 8);
        r2.x += __shfl_xor_sync(0xffffffffu, r2.x, 16);
        r2.y += __shfl_xor_sync(0xffffffffu, r2.y, 16);
        r2.z += __shfl_xor_sync(0xffffffffu, r2.z, 16);
        r2.w += __shfl_xor_sync(0xffffffffu, r2.w, 16);

        un = s_u1[n + 1];
        ax0.x += w0.x * un;  ax0.y += w0.y * un;
        ax0.z += w0.z * un;  ax0.w += w0.w * un;
        ax1.x += w1.x * un;  ax1.y += w1.y * un;
        ax1.z += w1.z * un;  ax1.w += w1.w * un;

        u2a = s_u2[(2 * cq) * NPB + n + 1];
        u2b = s_u2[(2 * cq + 1) * NPB + n + 1];
        am0.x += r2.x * u2a;  am0.y += r2.y * u2a;
        am0.z += r2.z * u2a;  am0.w += r2.w * u2a;
        am1.x += r2.x * u2b;  am1.y += r2.y * u2b;
        am1.z += r2.z * u2b;  am1.w += r2.w * u2b;
    }

    float4* gp = g_part + (size_t)(b * NBLK + blockIdx.x) * (2 * Cc * TQ);
    gp[(2 * cq) * TQ + q]               = ax0;
    gp[(2 * cq + 1) * TQ + q]           = ax1;
    gp[Cc * TQ + (2 * cq) * TQ + q]     = am0;
    gp[Cc * TQ + (2 * cq + 1) * TQ + q] = am1;
}

// ---------------------------------------------------------------------------
// Kernel 2: reduce 64 per-block partials -> g_xu1, g_M. (PDL-chained)
// ---------------------------------------------------------------------------
__global__ __launch_bounds__(512) void k_reduce2()
{
    __shared__ float4 red[4][128];

    const int t   = threadIdx.x;
    const int tx  = t & 127;
    const int ty  = t >> 7;
    const int idx = blockIdx.x * 128 + tx;
    const int b   = idx >> 10;
    const int rem = idx & 1023;

    PDL_WAIT();                 // g_part must be complete
    PDL_LAUNCH_DEPENDENTS();    // let k_sig launch early

    const float4* gp = g_part + (size_t)b * NBLK * (2 * Cc * TQ) + rem
                     + (size_t)ty * (NBLK / 4) * (2 * Cc * TQ);
    float4 s = make_float4(0.f, 0.f, 0.f, 0.f);
#pragma unroll 8
    for (int k = 0; k < NBLK / 4; k++) {
        float4 v = gp[(size_t)k * (2 * Cc * TQ)];
        s.x += v.x; s.y += v.y; s.z += v.z; s.w += v.w;
    }
    red[ty][tx] = s;
    __syncthreads();

    if (ty == 0) {
        float4 a = red[0][tx], b2 = red[1][tx], c = red[2][tx], d = red[3][tx];
        s.x = (a.x + b2.x) + (c.x + d.x);
        s.y = (a.y + b2.y) + (c.y + d.y);
        s.z = (a.z + b2.z) + (c.z + d.z);
        s.w = (a.w + b2.w) + (c.w + d.w);
        if (rem < Cc * TQ) ((float4*)g_xu1)[b * (Cc * TQ) + rem] = s;
        else               ((float4*)g_M  )[b * (Cc * TQ) + rem - Cc * TQ] = s;
    }
}

// ---------------------------------------------------------------------------
// Kernel 3: S[b,k,j] = tf32( sigmoid( sum_c x_u1[b,c,k]*M[b,c,j] + bias ) )
// ---------------------------------------------------------------------------
__global__ __launch_bounds__(256) void k_sig(const float* __restrict__ bias)
{
    __shared__ __align__(16) float s_M[Cc * Tt];
    __shared__ __align__(16) float s_X[KG * Cc];

    const int j  = threadIdx.x;
    const int b  = blockIdx.y;
    const int k0 = blockIdx.x * KG;

    // bias is an input, independent of predecessors: prefetch before the wait
    float pb[KG];
#pragma unroll
    for (int kl = 0; kl < KG; kl++) pb[kl] = bias[(k0 + kl) * Tt + j];

    PDL_WAIT();                 // g_xu1 / g_M must be complete
    PDL_LAUNCH_DEPENDENTS();    // let k_attn launch early

    for (int idx = j; idx < Cc * Tt; idx += 256)
        s_M[idx] = g_M[b * Cc * Tt + idx];
    if (j < KG * Cc) {
        int kl = j >> 3, c = j & 7;
        s_X[kl * Cc + c] = g_xu1[b * Cc * Tt + c * Tt + (k0 + kl)];
    }
    __syncthreads();

    float rm[Cc];
#pragma unroll
    for (int c = 0; c < Cc; c++) rm[c] = s_M[c * Tt + j];

#pragma unroll
    for (int kl = 0; kl < KG; kl++) {
        float4 x0 = *(const float4*)&s_X[kl * Cc + 0];
        float4 x1 = *(const float4*)&s_X[kl * Cc + 4];
        float p = pb[kl];
        p += x0.x * rm[0] + x0.y * rm[1] + x0.z * rm[2] + x0.w * rm[3]
           + x1.x * rm[4] + x1.y * rm[5] + x1.z * rm[6] + x1.w * rm[7];
        float e = __expf(-p);
        float s = __frcp_rn(1.f + e);
        g_S[b * Tt * Tt + (k0 + kl) * Tt + j] = __uint_as_float(f2tf32(s));
    }
}

// ---------------------------------------------------------------------------
// Kernel 4: E = v @ S via tf32 mma.sync (m16n8k8), fused softmax.
// 3-stage cp.async pipeline, KC=32 (8 chunks -> 8 barriers). v staged
// BEFORE the PDL wait (independent input) to overlap with k_sig's tail.
// ---------------------------------------------------------------------------
__global__ __launch_bounds__(256, 1) void k_attn(
    const float* __restrict__ v, float* __restrict__ out)
{
    __shared__ __align__(16) float s_S[NST][KC * SP];  // 3 x 33.8 KB
    __shared__ __align__(16) float s_V[Tt * VP];       // 24 KB, [k][i], tf32

    float* s_E = &s_S[0][0];   // 16 KB E plane aliases buffer 0 after loop

    const int tid  = threadIdx.x;
    const int lane = tid & 31;
    const int w    = tid >> 5;          // warp 0..7 -> n-range w*32
    const int gid  = lane >> 2;         // 0..7
    const int tig  = lane & 3;          // 0..3
    const int b    = blockIdx.y;
    const int i0   = blockIdx.x * TI;

    // stage v (tf32-rounded) BEFORE waiting on k_sig — independent input
#pragma unroll
    for (int il = 0; il < TI; il++)
        s_V[tid * VP + il] = __uint_as_float(f2tf32(v[(i0 + il) * Tt + tid]));

    PDL_WAIT();                 // g_S must be complete

    const char* Sg = (const char*)(g_S + (size_t)b * Tt * Tt);
    unsigned int sb[NST];
#pragma unroll
    for (int s = 0; s < NST; s++)
        sb[s] = (unsigned int)__cvta_generic_to_shared(&s_S[s][0]);

    // prologue: issue chunks 0..1 (each 32 rows x 256 floats = 2048 segs, 8/thread)
#pragma unroll
    for (int c = 0; c < NST - 1; c++) {
        const char* src = Sg + (size_t)c * KC * Tt * 4;
#pragma unroll
        for (int p = 0; p < 8; p++) {
            int s = p * 256 + tid;          // segment id 0..2047
            int row = s >> 6, c16 = s & 63;
            CP_ASYNC16(sb[c] + (row * SP + c16 * 4) * 4, src + s * 16);
        }
        CP_COMMIT();
    }

    float acc[4][4];
#pragma unroll
    for (int f = 0; f < 4; f++)
#pragma unroll
        for (int r = 0; r < 4; r++) acc[f][r] = 0.f;

    for (int ch = 0; ch < NCH; ch++) {
        if (ch < NCH - 1) { CP_WAIT(1); }   // chunk ch resident, 1 in flight
        else              { CP_WAIT(0); }
        __syncthreads();   // all readers of the buffer about to be refilled passed

        if (ch + NST - 1 < NCH) {   // issue chunk ch+2 into buffer (ch+2)%3
            const int cn = ch + NST - 1;
            const char* src = Sg + (size_t)cn * KC * Tt * 4;
            const unsigned int dst = sb[cn % NST];
#pragma unroll
            for (int p = 0; p < 8; p++) {
                int s = p * 256 + tid;
                int row = s >> 6, c16 = s & 63;
                CP_ASYNC16(dst + (row * SP + c16 * 4) * 4, src + s * 16);
            }
            CP_COMMIT();
        }

        const float* Sc = &s_S[ch % NST][0];
#pragma unroll
        for (int kh = 0; kh < 4; kh++) {
            const int kk8 = kh * 8;
            const int kb  = ch * KC + kk8;
            uint32_t a0 = __float_as_uint(s_V[(kb + tig) * VP + gid]);
            uint32_t a1 = __float_as_uint(s_V[(kb + tig) * VP + gid + 8]);
            uint32_t a2 = __float_as_uint(s_V[(kb + tig + 4) * VP + gid]);
            uint32_t a3 = __float_as_uint(s_V[(kb + tig + 4) * VP + gid + 8]);
#pragma unroll
            for (int f = 0; f < 4; f++) {
                const int n0 = w * 32 + f * 8;
                uint32_t b0 = __float_as_uint(Sc[(kk8 + tig) * SP + n0 + gid]);
                uint32_t b1 = __float_as_uint(Sc[(kk8 + tig + 4) * SP + n0 + gid]);
                mma_tf32(acc[f][0], acc[f][1], acc[f][2], acc[f][3],
                         a0, a1, a2, a3, b0, b1);
            }
        }
    }
    __syncthreads();  // all mma reads of s_S done before aliasing as s_E

    // write E: c0=(g,2t) c1=(g,2t+1) c2=(g+8,2t) c3=(g+8,2t+1)
#pragma unroll
    for (int f = 0; f < 4; f++) {
        const int n0 = w * 32 + f * 8;
        s_E[gid * Tt + n0 + 2 * tig]           = acc[f][0];
        s_E[gid * Tt + n0 + 2 * tig + 1]       = acc[f][1];
        s_E[(gid + 8) * Tt + n0 + 2 * tig]     = acc[f][2];
        s_E[(gid + 8) * Tt + n0 + 2 * tig + 1] = acc[f][3];
    }
    __syncthreads();

    // Softmax: 8 warps x 2 rows each
#pragma unroll
    for (int rr = 0; rr < 2; rr++) {
        const int row = w * 2 + rr;
        float m = -1e30f;
#pragma unroll
        for (int qi = 0; qi < Tt / 32; qi++)
            m = fmaxf(m, s_E[row * Tt + qi * 32 + lane]);
#pragma unroll
        for (int off = 16; off > 0; off >>= 1)
            m = fmaxf(m, __shfl_xor_sync(0xffffffffu, m, off));

        float e[Tt / 32];
        float sum = 0.f;
#pragma unroll
        for (int qi = 0; qi < Tt / 32; qi++) {
            e[qi] = __expf(s_E[row * Tt + qi * 32 + lane] - m);
            sum += e[qi];
        }
#pragma unroll
        for (int off = 16; off > 0; off >>= 1)
            sum += __shfl_xor_sync(0xffffffffu, sum, off);

        const float inv = __frcp_rn(sum);
        const size_t o = ((size_t)b * Tt + (i0 + row)) * Tt;
#pragma unroll
        for (int qi = 0; qi < Tt / 32; qi++)
            out[o + qi * 32 + lane] = e[qi] * inv;
    }
}

// ---------------------------------------------------------------------------
extern "C" void kernel_launch(void* const* d_in, const int* in_sizes, int n_in,
                              void* d_out, int out_size)
{
    const float* x  = (const float*)d_in[0];
    const float* u1 = (const float*)d_in[1];
    const float* u2 = (const float*)d_in[2];
    const float* u3 = (const float*)d_in[3];
    const float* bb = (const float*)d_in[4];
    const float* v  = (const float*)d_in[5];
    float* out = (float*)d_out;

    dim3 g1(NBLK, Bb);              // 512 blocks
    k_reduce<<<g1, 256>>>(x, u1, u2, u3);

    // PDL-chained dependents: launch may overlap predecessor's tail;
    // correctness enforced by griddepcontrol.wait inside each kernel.
    cudaLaunchAttribute at[1];
    at[0].id = cudaLaunchAttributeProgrammaticStreamSerialization;
    at[0].val.programmaticStreamSerializationAllowed = 1;

    cudaLaunchConfig_t cfg = {};
    cfg.attrs = at;
    cfg.numAttrs = 1;
    cfg.stream = 0;                 // legacy default stream (graph-captured)

    cfg.gridDim = dim3(64);
    cfg.blockDim = dim3(512);
    cudaLaunchKernelEx(&cfg, k_reduce2);

    cfg.gridDim = dim3(Tt / KG, Bb);
    cfg.blockDim = dim3(256);
    cudaLaunchKernelEx(&cfg, k_sig, bb);

    cfg.gridDim = dim3(Tt / TI, Bb);
    cfg.blockDim = dim3(256);
    cudaLaunchKernelEx(&cfg, k_attn, v, out);
}